// round 2
// baseline (speedup 1.0000x reference)
#include <cuda_runtime.h>
#include <cuda_bf16.h>
#include <cstdint>

#define BATCH 2
#define NANCH 261888
#define PRE_NMS 6000
#define PROP 1000
#define NMS_THR 0.7f
#define NBINS 4096
#define SCAP 12288       // per-batch sorted-candidate capacity
#define BUCKET_CAP 2048
#define NWORDS 94        // ceil(6000/64)

// ---------------- scratch (static device globals; no allocation) ----------------
__device__ int g_hist[BATCH * NBINS];
__device__ int g_offset[BATCH * NBINS];
__device__ int g_binfill[BATCH * NBINS];
__device__ int g_cutbin[BATCH];
__device__ unsigned long long g_sorted[BATCH * SCAP];
__device__ float4 g_boxes[BATCH * PRE_NMS];
__device__ unsigned long long g_mask[(size_t)BATCH * PRE_NMS * NWORDS]; // ~9MB

// ---------------- kernels ----------------

__global__ void zero_kernel() {
    int t = blockIdx.x * blockDim.x + threadIdx.x;
    if (t < BATCH * NBINS) { g_hist[t] = 0; g_binfill[t] = 0; }
    if (t < BATCH) g_cutbin[t] = 0;
}

__device__ __forceinline__ int score_bin(float s) {
    int b = (int)(s * (float)NBINS);
    if (b < 0) b = 0;
    if (b > NBINS - 1) b = NBINS - 1;
    return b;
}

__global__ void hist_kernel(const float2* __restrict__ cls) {
    __shared__ int h[BATCH * NBINS];
    for (int t = threadIdx.x; t < BATCH * NBINS; t += blockDim.x) h[t] = 0;
    __syncthreads();
    const long long total = (long long)BATCH * NANCH;
    for (long long t = blockIdx.x * (long long)blockDim.x + threadIdx.x; t < total;
         t += (long long)gridDim.x * blockDim.x) {
        int b = (int)(t / NANCH);
        float s = cls[t].y;
        atomicAdd(&h[b * NBINS + score_bin(s)], 1);
    }
    __syncthreads();
    for (int t = threadIdx.x; t < BATCH * NBINS; t += blockDim.x)
        if (h[t]) atomicAdd(&g_hist[t], h[t]);
}

// per-batch exclusive suffix-scan of the histogram -> bucket offsets, plus cutbin
__global__ void scan_kernel() {
    int b = blockIdx.x, t = threadIdx.x; // 1024 threads, 4 bins each
    int base = b * NBINS + t * 4;
    int h0 = g_hist[base + 0], h1 = g_hist[base + 1];
    int h2 = g_hist[base + 2], h3 = g_hist[base + 3];
    int sum = h0 + h1 + h2 + h3;
    __shared__ int sA[1024], sB[1024];
    sA[t] = sum;
    __syncthreads();
    int* src = sA; int* dst = sB;
    for (int d = 1; d < 1024; d <<= 1) {
        int v = src[t];
        if (t + d < 1024) v += src[t + d];
        dst[t] = v;
        __syncthreads();
        int* tmp = src; src = dst; dst = tmp;
    }
    int incl = src[t];          // inclusive suffix over chunks
    int excl = incl - sum;      // items in strictly-higher chunks
    int off3 = excl;
    int off2 = off3 + h3;
    int off1 = off2 + h2;
    int off0 = off1 + h1;
    g_offset[base + 0] = off0; g_offset[base + 1] = off1;
    g_offset[base + 2] = off2; g_offset[base + 3] = off3;
    // cutbin = largest bin whose inclusive suffix count >= PRE_NMS
    if (off3 + h3 >= PRE_NMS) atomicMax(&g_cutbin[b], t * 4 + 3);
    else if (off2 + h2 >= PRE_NMS) atomicMax(&g_cutbin[b], t * 4 + 2);
    else if (off1 + h1 >= PRE_NMS) atomicMax(&g_cutbin[b], t * 4 + 1);
    else if (off0 + h0 >= PRE_NMS) atomicMax(&g_cutbin[b], t * 4 + 0);
}

__global__ void scatter_kernel(const float2* __restrict__ cls) {
    long long t = blockIdx.x * (long long)blockDim.x + threadIdx.x;
    const long long total = (long long)BATCH * NANCH;
    if (t >= total) return;
    int b = (int)(t / NANCH);
    int i = (int)(t - (long long)b * NANCH);
    float s = cls[t].y;
    int q = score_bin(s);
    if (q >= g_cutbin[b]) {
        int pos = g_offset[b * NBINS + q] + atomicAdd(&g_binfill[b * NBINS + q], 1);
        if (pos < SCAP) {
            unsigned int sb = __float_as_uint(s); // s in [0,1): bit-monotonic
            g_sorted[b * SCAP + pos] =
                ((unsigned long long)sb << 32) | (unsigned long long)(0xFFFFFFFFu - (unsigned)i);
        }
    }
}

// sort each bucket (descending) independently; buckets are ~64 keys
__global__ void bucket_sort_kernel() {
    int bin = blockIdx.x, b = blockIdx.y;
    if (bin < g_cutbin[b]) return;
    int cnt = g_hist[b * NBINS + bin];
    if (cnt <= 1) return;
    if (cnt > BUCKET_CAP) cnt = BUCKET_CAP;
    int off = g_offset[b * NBINS + bin];
    __shared__ unsigned long long s[BUCKET_CAP];
    int P = 1;
    while (P < cnt) P <<= 1;
    unsigned long long* src = g_sorted + (size_t)b * SCAP + off;
    for (int t = threadIdx.x; t < P; t += blockDim.x)
        s[t] = (t < cnt) ? src[t] : 0ULL;
    __syncthreads();
    for (int k = 2; k <= P; k <<= 1) {
        for (int j = k >> 1; j > 0; j >>= 1) {
            for (int i = threadIdx.x; i < P; i += blockDim.x) {
                int ixj = i ^ j;
                if (ixj > i) {
                    bool dir = ((i & k) == 0); // descending segments
                    unsigned long long a = s[i], c = s[ixj];
                    if ((a < c) == dir) { s[i] = c; s[ixj] = a; }
                }
            }
            __syncthreads();
        }
    }
    for (int t = threadIdx.x; t < cnt; t += blockDim.x) src[t] = s[t];
}

__global__ void boxes_kernel(const float* __restrict__ rpn_bbox,
                             const float* __restrict__ anchors) {
    int t = blockIdx.x * blockDim.x + threadIdx.x;
    if (t >= BATCH * PRE_NMS) return;
    int b = t / PRE_NMS;
    int r = t - b * PRE_NMS;
    unsigned int low = (unsigned int)(g_sorted[(size_t)b * SCAP + r] & 0xFFFFFFFFu);
    int idx = (int)(0xFFFFFFFFu - low);
    size_t base = ((size_t)b * NANCH + (size_t)idx) * 4;
    float a0 = anchors[base + 0], a1 = anchors[base + 1];
    float a2 = anchors[base + 2], a3 = anchors[base + 3];
    float d0 = rpn_bbox[base + 0] * 0.1f;
    float d1 = rpn_bbox[base + 1] * 0.1f;
    float d2 = rpn_bbox[base + 2] * 0.2f;
    float d3 = rpn_bbox[base + 3] * 0.2f;
    float h = a2 - a0, w = a3 - a1;
    float cy = a0 + 0.5f * h + d0 * h;
    float cx = a1 + 0.5f * w + d1 * w;
    h = h * expf(d2);
    w = w * expf(d3);
    float y1 = cy - 0.5f * h;
    float x1 = cx - 0.5f * w;
    float y2 = y1 + h;
    float x2 = x1 + w;
    y1 = fminf(fmaxf(y1, 0.f), 1.f);
    x1 = fminf(fmaxf(x1, 0.f), 1.f);
    y2 = fminf(fmaxf(y2, 0.f), 1.f);
    x2 = fminf(fmaxf(x2, 0.f), 1.f);
    g_boxes[t] = make_float4(y1, x1, y2, x2);
}

// 64x64 tile IoU>thr bitmask
__global__ void mask_kernel() {
    int b = blockIdx.z;
    int row0 = blockIdx.y * 64;
    int col0 = blockIdx.x * 64;
    __shared__ float4 cbox[64];
    int t = threadIdx.x;
    int c = col0 + t;
    cbox[t] = (c < PRE_NMS) ? g_boxes[b * PRE_NMS + c] : make_float4(0.f, 0.f, 0.f, 0.f);
    __syncthreads();
    int r = row0 + t;
    if (r >= PRE_NMS) return;
    float4 rb = g_boxes[b * PRE_NMS + r];
    float areaR = (rb.z - rb.x) * (rb.w - rb.y);
    unsigned long long bits = 0ULL;
#pragma unroll 8
    for (int jj = 0; jj < 64; ++jj) {
        float4 cb = cbox[jj];
        float areaC = (cb.z - cb.x) * (cb.w - cb.y);
        float ih = fmaxf(fminf(rb.z, cb.z) - fmaxf(rb.x, cb.x), 0.f);
        float iw = fmaxf(fminf(rb.w, cb.w) - fmaxf(rb.y, cb.y), 0.f);
        float inter = ih * iw;
        float iou = inter / (areaR + areaC - inter + 1e-8f);
        if (iou > NMS_THR) bits |= (1ULL << jj);
    }
    g_mask[((size_t)b * PRE_NMS + r) * NWORDS + blockIdx.x] = bits;
}

// one warp per batch: exact sequential greedy NMS, depth-8 prefetch,
// replicated current-word (shfl only at 64-row boundaries)
__global__ void nms_serial_kernel(float* __restrict__ out) {
    int b = blockIdx.x;
    int lane = threadIdx.x; // 32 threads
    const unsigned long long* M = g_mask + (size_t)b * PRE_NMS * NWORDS;
    __shared__ int list[PROP];
    const int w0 = lane, w1 = lane + 32, w2 = lane + 64;
    const bool v1 = (w1 < NWORDS), v2 = (w2 < NWORDS);
    unsigned long long rem0 = 0, rem1 = 0, rem2 = 0, rem_cur = 0;
    const int D = 8;
    unsigned long long nb0[D], nb1[D], nb2[D], nd[D];
#pragma unroll
    for (int u = 0; u < D; ++u) {
        const unsigned long long* row = M + (size_t)u * NWORDS;
        nb0[u] = row[w0];
        nb1[u] = v1 ? row[w1] : 0ULL;
        nb2[u] = v2 ? row[w2] : 0ULL;
        nd[u] = row[0]; // (u>>6)==0 for u<8
    }
    int kc = 0;
    for (int ii = 0; ii < PRE_NMS; ii += D) {
#pragma unroll
        for (int u = 0; u < D; ++u) {
            int i = ii + u;
            unsigned long long c0 = nb0[u], c1 = nb1[u], c2 = nb2[u], cd = nd[u];
            int ip = i + D;
            if (ip < PRE_NMS) {
                const unsigned long long* row = M + (size_t)ip * NWORDS;
                nb0[u] = row[w0];
                nb1[u] = v1 ? row[w1] : 0ULL;
                nb2[u] = v2 ? row[w2] : 0ULL;
                nd[u] = row[ip >> 6];
            }
            if ((i & 63) == 0) {
                int word = i >> 6;
                int src = word & 31;
                unsigned long long mine = (word < 32) ? rem0 : ((word < 64) ? rem1 : rem2);
                rem_cur = __shfl_sync(0xffffffffu, mine, src);
            }
            if (!((rem_cur >> (i & 63)) & 1ULL)) {
                if (lane == 0 && kc < PROP) list[kc] = i;
                kc++;
                rem0 |= c0; rem1 |= c1; rem2 |= c2;
                rem_cur |= cd;
                if (kc >= PROP) goto done;
            }
        }
    }
done:
    __syncwarp();
    const float4* bx = g_boxes + b * PRE_NMS;
    float4* o = (float4*)(out + (size_t)b * PROP * 4);
    for (int r = lane; r < PROP; r += 32) {
        float4 v = make_float4(0.f, 0.f, 0.f, 0.f);
        if (r < kc) v = bx[list[r]];
        o[r] = v;
    }
}

// ---------------- launch ----------------
extern "C" void kernel_launch(void* const* d_in, const int* in_sizes, int n_in,
                              void* d_out, int out_size) {
    (void)in_sizes; (void)n_in; (void)out_size;
    const float2* cls = (const float2*)d_in[0];     // (B,N,2)
    const float* rpn_bbox = (const float*)d_in[1];  // (B,N,4)
    const float* anchors = (const float*)d_in[2];   // (B,N,4)
    float* out = (float*)d_out;                     // (B,1000,4)

    zero_kernel<<<(BATCH * NBINS + 1023) / 1024, 1024>>>();
    hist_kernel<<<256, 512>>>(cls);
    scan_kernel<<<BATCH, 1024>>>();
    {
        long long total = (long long)BATCH * NANCH;
        int blocks = (int)((total + 511) / 512);
        scatter_kernel<<<blocks, 512>>>(cls);
    }
    {
        dim3 grid(NBINS, BATCH);
        bucket_sort_kernel<<<grid, 256>>>();
    }
    boxes_kernel<<<(BATCH * PRE_NMS + 255) / 256, 256>>>(rpn_bbox, anchors);
    {
        dim3 grid(NWORDS, (PRE_NMS + 63) / 64, BATCH);
        mask_kernel<<<grid, 64>>>();
    }
    nms_serial_kernel<<<BATCH, 32>>>(out);
}

// round 3
// speedup vs baseline: 3.8205x; 3.8205x over previous
#include <cuda_runtime.h>
#include <cuda_bf16.h>
#include <cstdint>

#define BATCH 2
#define NANCH 261888
#define PRE_NMS 6000
#define PRE2 2048          // prefix length for fast-path NMS
#define NW2 (PRE2 / 64)    // 32 words per prefix row
#define PROP 1000
#define NMS_THR 0.7f
#define NBINS 4096
#define SCAP 12288
#define BUCKET_CAP 2048
#define NWORDS 94          // ceil(6000/64) for fallback

typedef unsigned long long u64;

// ---------------- scratch (zero at module load; re-zeroed by cleanup each call) ----
__device__ int g_hist[BATCH * NBINS];
__device__ int g_offset[BATCH * NBINS];
__device__ int g_binfill[BATCH * NBINS];
__device__ int g_cutbin[BATCH];
__device__ int g_done[BATCH];
__device__ u64 g_sorted[BATCH * SCAP];
__device__ float4 g_boxes[BATCH * PRE_NMS];
__device__ u64 g_mask2[BATCH * PRE2 * NW2];                 // 1 MB prefix mask
__device__ u64 g_mask[(size_t)BATCH * PRE_NMS * NWORDS];    // 9 MB fallback mask

// ---------------- helpers ----------------
__device__ __forceinline__ int score_bin(float s) {
    int b = (int)(s * (float)NBINS);
    if (b < 0) b = 0;
    if (b > NBINS - 1) b = NBINS - 1;
    return b;
}

// ---------------- 1: histogram ----------------
__global__ void hist_kernel(const float2* __restrict__ cls) {
    __shared__ int h[BATCH * NBINS];
    for (int t = threadIdx.x; t < BATCH * NBINS; t += blockDim.x) h[t] = 0;
    __syncthreads();
    const long long total = (long long)BATCH * NANCH;
    for (long long t = blockIdx.x * (long long)blockDim.x + threadIdx.x; t < total;
         t += (long long)gridDim.x * blockDim.x) {
        int b = (int)(t / NANCH);
        atomicAdd(&h[b * NBINS + score_bin(cls[t].y)], 1);
    }
    __syncthreads();
    for (int t = threadIdx.x; t < BATCH * NBINS; t += blockDim.x)
        if (h[t]) atomicAdd(&g_hist[t], h[t]);
}

// ---------------- 2: suffix scan + cutbin ----------------
__global__ void scan_kernel() {
    int b = blockIdx.x, t = threadIdx.x; // 1024 threads, 4 bins each
    int base = b * NBINS + t * 4;
    int h0 = g_hist[base + 0], h1 = g_hist[base + 1];
    int h2 = g_hist[base + 2], h3 = g_hist[base + 3];
    int sum = h0 + h1 + h2 + h3;
    __shared__ int sA[1024], sB[1024];
    sA[t] = sum;
    __syncthreads();
    int* src = sA; int* dst = sB;
    for (int d = 1; d < 1024; d <<= 1) {
        int v = src[t];
        if (t + d < 1024) v += src[t + d];
        dst[t] = v;
        __syncthreads();
        int* tmp = src; src = dst; dst = tmp;
    }
    int incl = src[t];
    int excl = incl - sum;
    int off3 = excl;
    int off2 = off3 + h3;
    int off1 = off2 + h2;
    int off0 = off1 + h1;
    g_offset[base + 0] = off0; g_offset[base + 1] = off1;
    g_offset[base + 2] = off2; g_offset[base + 3] = off3;
    if (off3 + h3 >= PRE_NMS) atomicMax(&g_cutbin[b], t * 4 + 3);
    else if (off2 + h2 >= PRE_NMS) atomicMax(&g_cutbin[b], t * 4 + 2);
    else if (off1 + h1 >= PRE_NMS) atomicMax(&g_cutbin[b], t * 4 + 1);
    else if (off0 + h0 >= PRE_NMS) atomicMax(&g_cutbin[b], t * 4 + 0);
}

// ---------------- 3: scatter candidates to bucket ranges ----------------
__global__ void scatter_kernel(const float2* __restrict__ cls) {
    long long t = blockIdx.x * (long long)blockDim.x + threadIdx.x;
    const long long total = (long long)BATCH * NANCH;
    if (t >= total) return;
    int b = (int)(t / NANCH);
    int i = (int)(t - (long long)b * NANCH);
    float s = cls[t].y;
    int q = score_bin(s);
    if (q >= g_cutbin[b]) {
        int pos = g_offset[b * NBINS + q] + atomicAdd(&g_binfill[b * NBINS + q], 1);
        if (pos < SCAP) {
            unsigned int sb = __float_as_uint(s);
            g_sorted[b * SCAP + pos] =
                ((u64)sb << 32) | (u64)(0xFFFFFFFFu - (unsigned)i);
        }
    }
}

// ---------------- 4: per-bucket sort + box decode (fused) ----------------
__global__ void sortbox_kernel(const float* __restrict__ rpn_bbox,
                               const float* __restrict__ anchors) {
    int bin = blockIdx.x, b = blockIdx.y;
    if (bin < g_cutbin[b]) return;
    int cnt = g_hist[b * NBINS + bin];
    if (cnt <= 0) return;
    if (cnt > BUCKET_CAP) cnt = BUCKET_CAP;
    int off = g_offset[b * NBINS + bin];
    if (off >= PRE_NMS) return;
    __shared__ u64 s[BUCKET_CAP];
    int P = 1;
    while (P < cnt) P <<= 1;
    const u64* src = g_sorted + (size_t)b * SCAP + off;
    for (int t = threadIdx.x; t < P; t += blockDim.x)
        s[t] = (t < cnt) ? src[t] : 0ULL;
    __syncthreads();
    if (cnt > 1) {
        for (int k = 2; k <= P; k <<= 1) {
            for (int j = k >> 1; j > 0; j >>= 1) {
                for (int i = threadIdx.x; i < P; i += blockDim.x) {
                    int ixj = i ^ j;
                    if (ixj > i) {
                        bool dir = ((i & k) == 0);
                        u64 a = s[i], c = s[ixj];
                        if ((a < c) == dir) { s[i] = c; s[ixj] = a; }
                    }
                }
                __syncthreads();
            }
        }
    }
    // decode boxes for ranks < PRE_NMS
    for (int t = threadIdx.x; t < cnt; t += blockDim.x) {
        int rank = off + t;
        if (rank >= PRE_NMS) continue;
        unsigned int low = (unsigned int)(s[t] & 0xFFFFFFFFu);
        int idx = (int)(0xFFFFFFFFu - low);
        size_t base = ((size_t)b * NANCH + (size_t)idx) * 4;
        float a0 = anchors[base + 0], a1 = anchors[base + 1];
        float a2 = anchors[base + 2], a3 = anchors[base + 3];
        float d0 = rpn_bbox[base + 0] * 0.1f;
        float d1 = rpn_bbox[base + 1] * 0.1f;
        float d2 = rpn_bbox[base + 2] * 0.2f;
        float d3 = rpn_bbox[base + 3] * 0.2f;
        float h = a2 - a0, w = a3 - a1;
        float cy = a0 + 0.5f * h + d0 * h;
        float cx = a1 + 0.5f * w + d1 * w;
        h = h * expf(d2);
        w = w * expf(d3);
        float y1 = cy - 0.5f * h;
        float x1 = cx - 0.5f * w;
        float y2 = y1 + h;
        float x2 = x1 + w;
        y1 = fminf(fmaxf(y1, 0.f), 1.f);
        x1 = fminf(fmaxf(x1, 0.f), 1.f);
        y2 = fminf(fmaxf(y2, 0.f), 1.f);
        x2 = fminf(fmaxf(x2, 0.f), 1.f);
        g_boxes[b * PRE_NMS + rank] = make_float4(y1, x1, y2, x2);
    }
}

// ---------------- 5: prefix IoU bitmask (2048 x 2048) ----------------
__global__ void maskpre_kernel() {
    int b = blockIdx.z;
    int row0 = blockIdx.y * 128;
    int col0 = blockIdx.x * 64;
    __shared__ float4 cbox[64];
    __shared__ float carea[64];
    int t = threadIdx.x; // 128 threads
    if (t < 64) {
        float4 cb = g_boxes[b * PRE_NMS + col0 + t];
        cbox[t] = cb;
        carea[t] = (cb.z - cb.x) * (cb.w - cb.y);
    }
    __syncthreads();
    int r = row0 + t;
    float4 rb = g_boxes[b * PRE_NMS + r];
    float areaR = (rb.z - rb.x) * (rb.w - rb.y);
    u64 bits = 0ULL;
#pragma unroll 8
    for (int jj = 0; jj < 64; ++jj) {
        float4 cb = cbox[jj];
        float ih = fmaxf(fminf(rb.z, cb.z) - fmaxf(rb.x, cb.x), 0.f);
        float iw = fmaxf(fminf(rb.w, cb.w) - fmaxf(rb.y, cb.y), 0.f);
        float inter = ih * iw;
        float iou = inter / (areaR + carea[jj] - inter + 1e-8f);
        if (iou > NMS_THR) bits |= (1ULL << jj);
    }
    g_mask2[(b * PRE2 + r) * NW2 + blockIdx.x] = bits;
}

// ---------------- 6: prefix serial NMS (1 warp/batch, 1 u64 state per lane) ----
__global__ void nmspre_kernel(float* __restrict__ out) {
    int b = blockIdx.x;
    int lane = threadIdx.x; // 32
    const u64* M = g_mask2 + (size_t)b * PRE2 * NW2;
    __shared__ int list[PROP];
    u64 rem = 0, remcur = 0;
    const int D = 8;
    u64 buf[D];
#pragma unroll
    for (int u = 0; u < D; ++u) buf[u] = M[u * NW2 + lane];
    int kc = 0;
    for (int ii = 0; ii < PRE2; ii += D) {
#pragma unroll
        for (int u = 0; u < D; ++u) {
            int i = ii + u;
            u64 c = buf[u];
            int ip = i + D;
            if (ip < PRE2) buf[u] = M[(size_t)ip * NW2 + lane];
            if ((i & 63) == 0) remcur = __shfl_sync(0xffffffffu, rem, i >> 6);
            if (!((remcur >> (i & 63)) & 1ULL)) {
                if (lane == 0 && kc < PROP) list[kc] = i;
                kc++;
                rem |= c;
                remcur |= __shfl_sync(0xffffffffu, c, i >> 6);
                if (kc >= PROP) goto done;
            }
        }
    }
done:
    __syncwarp();
    if (kc >= PROP) {
        if (lane == 0) g_done[b] = 1;
        const float4* bx = g_boxes + b * PRE_NMS;
        float4* o = (float4*)(out + (size_t)b * PROP * 4);
        for (int r = lane; r < PROP; r += 32) o[r] = bx[list[r]];
    } else {
        if (lane == 0) g_done[b] = 0;
    }
}

// ---------------- 7: fallback full mask (flag-guarded) ----------------
__global__ void fbmask_kernel() {
    int b = blockIdx.z;
    if (g_done[b]) return;
    int row0 = blockIdx.y * 128;
    int col0 = blockIdx.x * 64;
    __shared__ float4 cbox[64];
    __shared__ float carea[64];
    int t = threadIdx.x; // 128
    if (t < 64) {
        int c = col0 + t;
        float4 cb = (c < PRE_NMS) ? g_boxes[b * PRE_NMS + c] : make_float4(0.f, 0.f, 0.f, 0.f);
        cbox[t] = cb;
        carea[t] = (cb.z - cb.x) * (cb.w - cb.y);
    }
    __syncthreads();
    int r = row0 + t;
    if (r >= PRE_NMS) return;
    float4 rb = g_boxes[b * PRE_NMS + r];
    float areaR = (rb.z - rb.x) * (rb.w - rb.y);
    u64 bits = 0ULL;
#pragma unroll 8
    for (int jj = 0; jj < 64; ++jj) {
        float4 cb = cbox[jj];
        float ih = fmaxf(fminf(rb.z, cb.z) - fmaxf(rb.x, cb.x), 0.f);
        float iw = fmaxf(fminf(rb.w, cb.w) - fmaxf(rb.y, cb.y), 0.f);
        float inter = ih * iw;
        float iou = inter / (areaR + carea[jj] - inter + 1e-8f);
        if (iou > NMS_THR) bits |= (1ULL << jj);
    }
    g_mask[((size_t)b * PRE_NMS + r) * NWORDS + blockIdx.x] = bits;
}

// ---------------- 8: fallback full serial NMS (flag-guarded) ----------------
__global__ void fbnms_kernel(float* __restrict__ out) {
    int b = blockIdx.x;
    if (g_done[b]) return;
    int lane = threadIdx.x;
    const u64* M = g_mask + (size_t)b * PRE_NMS * NWORDS;
    u64 rem0 = 0, rem1 = 0, rem2 = 0;
    __shared__ int list[PROP];
    int kc = 0;
    int w0 = lane, w1 = lane + 32, w2 = lane + 64;
    for (int i = 0; i < PRE_NMS; ++i) {
        const u64* row = M + (size_t)i * NWORDS;
        u64 c0 = row[w0];
        u64 c1 = (w1 < NWORDS) ? row[w1] : 0ULL;
        u64 c2 = (w2 < NWORDS) ? row[w2] : 0ULL;
        int word = i >> 6, bit = i & 63;
        int src = word & 31, slot = word >> 5;
        u64 mine = (slot == 0) ? rem0 : ((slot == 1) ? rem1 : rem2);
        u64 v = __shfl_sync(0xffffffffu, mine, src);
        if (!((v >> bit) & 1ULL)) {
            if (lane == 0 && kc < PROP) list[kc] = i;
            kc++;
            rem0 |= c0; rem1 |= c1; rem2 |= c2;
            if (kc >= PROP) break;
        }
    }
    __syncwarp();
    const float4* bx = g_boxes + b * PRE_NMS;
    float4* o = (float4*)(out + (size_t)b * PROP * 4);
    for (int r = lane; r < PROP; r += 32) {
        float4 v = make_float4(0.f, 0.f, 0.f, 0.f);
        if (r < kc) v = bx[list[r]];
        o[r] = v;
    }
}

// ---------------- 9: cleanup — re-zero scratch for next invocation ----------------
__global__ void cleanup_kernel() {
    int t = blockIdx.x * blockDim.x + threadIdx.x;
    if (t < BATCH * NBINS) { g_hist[t] = 0; g_binfill[t] = 0; }
    if (t < BATCH) g_cutbin[t] = 0;
}

// ---------------- launch ----------------
extern "C" void kernel_launch(void* const* d_in, const int* in_sizes, int n_in,
                              void* d_out, int out_size) {
    (void)in_sizes; (void)n_in; (void)out_size;
    const float2* cls = (const float2*)d_in[0];
    const float* rpn_bbox = (const float*)d_in[1];
    const float* anchors = (const float*)d_in[2];
    float* out = (float*)d_out;

    hist_kernel<<<256, 512>>>(cls);
    scan_kernel<<<BATCH, 1024>>>();
    {
        long long total = (long long)BATCH * NANCH;
        scatter_kernel<<<(int)((total + 511) / 512), 512>>>(cls);
    }
    {
        dim3 grid(NBINS, BATCH);
        sortbox_kernel<<<grid, 256>>>(rpn_bbox, anchors);
    }
    {
        dim3 grid(NW2, PRE2 / 128, BATCH);       // (32, 16, 2)
        maskpre_kernel<<<grid, 128>>>();
    }
    nmspre_kernel<<<BATCH, 32>>>(out);
    {
        dim3 grid(NWORDS, (PRE_NMS + 127) / 128, BATCH); // (94, 47, 2)
        fbmask_kernel<<<grid, 128>>>();
    }
    fbnms_kernel<<<BATCH, 32>>>(out);
    cleanup_kernel<<<(BATCH * NBINS + 1023) / 1024, 1024>>>();
}

// round 4
// speedup vs baseline: 5.7783x; 1.5124x over previous
#include <cuda_runtime.h>
#include <cuda_bf16.h>
#include <cstdint>

#define BATCH 2
#define NANCH 261888
#define PRE_NMS 6000
#define PRE2 2048          // prefix length for fast-path NMS
#define NW2 (PRE2 / 64)    // 32 words per prefix row
#define PROP 1000
#define NMS_THR 0.7f
#define NBINS 4096
#define SCAP 12288
#define BUCKET_CAP 2048
#define NWORDS 94          // ceil(6000/64) for fallback

typedef unsigned long long u64;

// ---------------- scratch (zero at module load; re-zeroed by tail of fbnms) ------
__device__ int g_hist[BATCH * NBINS];
__device__ int g_offset[BATCH * NBINS];
__device__ int g_binfill[BATCH * NBINS];
__device__ int g_cutbin[BATCH];
__device__ int g_done[BATCH];
__device__ unsigned int g_ticket;
__device__ u64 g_sorted[BATCH * SCAP];
__device__ float4 g_boxes[BATCH * PRE_NMS];
__device__ u64 g_mask2[BATCH * PRE2 * NW2];                 // 1 MB prefix mask
__device__ u64 g_mask[(size_t)BATCH * PRE_NMS * NWORDS];    // 9 MB fallback mask

// ---------------- helpers ----------------
__device__ __forceinline__ int score_bin(float s) {
    int b = (int)(s * (float)NBINS);
    if (b < 0) b = 0;
    if (b > NBINS - 1) b = NBINS - 1;
    return b;
}

// ---------------- 1: histogram + fused suffix-scan (last-block) ----------------
__global__ void hist_kernel(const float4* __restrict__ cls4) {
    __shared__ int h[BATCH * NBINS];
    for (int t = threadIdx.x; t < BATCH * NBINS; t += blockDim.x) h[t] = 0;
    __syncthreads();
    const int total4 = BATCH * NANCH / 2;   // float4 = 2 anchors
    const int half = NANCH / 2;
    for (int t = blockIdx.x * blockDim.x + threadIdx.x; t < total4;
         t += gridDim.x * blockDim.x) {
        int b = t / half;
        float4 v = cls4[t];
        atomicAdd(&h[b * NBINS + score_bin(v.y)], 1);
        atomicAdd(&h[b * NBINS + score_bin(v.w)], 1);
    }
    __syncthreads();
    for (int t = threadIdx.x; t < BATCH * NBINS; t += blockDim.x)
        if (h[t]) atomicAdd(&g_hist[t], h[t]);

    // last block performs the suffix scan
    __threadfence();
    __shared__ int is_last;
    if (threadIdx.x == 0)
        is_last = (atomicAdd(&g_ticket, 1u) == gridDim.x - 1) ? 1 : 0;
    __syncthreads();
    if (!is_last) return;

    __shared__ int sA[512], sB[512];
    for (int b = 0; b < BATCH; ++b) {
        int t = threadIdx.x;   // 512 threads, 8 bins each
        int base = b * NBINS + t * 8;
        int hh[8];
        int sum = 0;
#pragma unroll
        for (int k = 0; k < 8; ++k) { hh[k] = g_hist[base + k]; sum += hh[k]; }
        sA[t] = sum;
        __syncthreads();
        int* src = sA; int* dst = sB;
        for (int d = 1; d < 512; d <<= 1) {
            int v = src[t];
            if (t + d < 512) v += src[t + d];
            dst[t] = v;
            __syncthreads();
            int* tmp = src; src = dst; dst = tmp;
        }
        int excl = src[t] - sum;   // items in strictly-higher chunks
        int off[8];
        off[7] = excl;
#pragma unroll
        for (int k = 6; k >= 0; --k) off[k] = off[k + 1] + hh[k + 1];
#pragma unroll
        for (int k = 0; k < 8; ++k) g_offset[base + k] = off[k];
        int cand = -1;
#pragma unroll
        for (int k = 7; k >= 0; --k)
            if (cand < 0 && off[k] + hh[k] >= PRE_NMS) cand = t * 8 + k;
        if (cand >= 0) atomicMax(&g_cutbin[b], cand);
        __syncthreads();
    }
}

// ---------------- 2: scatter candidates to bucket ranges (float4) --------------
__global__ void scatter_kernel(const float4* __restrict__ cls4) {
    const int total4 = BATCH * NANCH / 2;
    const int half = NANCH / 2;
    int t = blockIdx.x * blockDim.x + threadIdx.x;
    if (t >= total4) return;
    int b = t / half;
    int i0 = (t - b * half) * 2;
    float4 v = cls4[t];
    int cut = g_cutbin[b];
#pragma unroll
    for (int e = 0; e < 2; ++e) {
        float s = e ? v.w : v.y;
        int i = i0 + e;
        int q = score_bin(s);
        if (q >= cut) {
            int pos = g_offset[b * NBINS + q] + atomicAdd(&g_binfill[b * NBINS + q], 1);
            if (pos < SCAP) {
                unsigned int sb = __float_as_uint(s);
                g_sorted[b * SCAP + pos] =
                    ((u64)sb << 32) | (u64)(0xFFFFFFFFu - (unsigned)i);
            }
        }
    }
}

// ---------------- 3: per-bucket sort + box decode (fused) ----------------
__global__ void sortbox_kernel(const float* __restrict__ rpn_bbox,
                               const float* __restrict__ anchors) {
    int bin = blockIdx.x, b = blockIdx.y;
    if (bin < g_cutbin[b]) return;
    int cnt = g_hist[b * NBINS + bin];
    if (cnt <= 0) return;
    if (cnt > BUCKET_CAP) cnt = BUCKET_CAP;
    int off = g_offset[b * NBINS + bin];
    if (off >= PRE_NMS) return;
    __shared__ u64 s[BUCKET_CAP];
    int P = 1;
    while (P < cnt) P <<= 1;
    const u64* src = g_sorted + (size_t)b * SCAP + off;
    for (int t = threadIdx.x; t < P; t += blockDim.x)
        s[t] = (t < cnt) ? src[t] : 0ULL;
    __syncthreads();
    if (cnt > 1) {
        for (int k = 2; k <= P; k <<= 1) {
            for (int j = k >> 1; j > 0; j >>= 1) {
                for (int i = threadIdx.x; i < P; i += blockDim.x) {
                    int ixj = i ^ j;
                    if (ixj > i) {
                        bool dir = ((i & k) == 0);
                        u64 a = s[i], c = s[ixj];
                        if ((a < c) == dir) { s[i] = c; s[ixj] = a; }
                    }
                }
                __syncthreads();
            }
        }
    }
    for (int t = threadIdx.x; t < cnt; t += blockDim.x) {
        int rank = off + t;
        if (rank >= PRE_NMS) continue;
        unsigned int low = (unsigned int)(s[t] & 0xFFFFFFFFu);
        int idx = (int)(0xFFFFFFFFu - low);
        size_t base = ((size_t)b * NANCH + (size_t)idx) * 4;
        float a0 = anchors[base + 0], a1 = anchors[base + 1];
        float a2 = anchors[base + 2], a3 = anchors[base + 3];
        float d0 = rpn_bbox[base + 0] * 0.1f;
        float d1 = rpn_bbox[base + 1] * 0.1f;
        float d2 = rpn_bbox[base + 2] * 0.2f;
        float d3 = rpn_bbox[base + 3] * 0.2f;
        float h = a2 - a0, w = a3 - a1;
        float cy = a0 + 0.5f * h + d0 * h;
        float cx = a1 + 0.5f * w + d1 * w;
        h = h * expf(d2);
        w = w * expf(d3);
        float y1 = cy - 0.5f * h;
        float x1 = cx - 0.5f * w;
        float y2 = y1 + h;
        float x2 = x1 + w;
        y1 = fminf(fmaxf(y1, 0.f), 1.f);
        x1 = fminf(fmaxf(x1, 0.f), 1.f);
        y2 = fminf(fmaxf(y2, 0.f), 1.f);
        x2 = fminf(fmaxf(x2, 0.f), 1.f);
        g_boxes[b * PRE_NMS + rank] = make_float4(y1, x1, y2, x2);
    }
}

// ---------------- 4: prefix IoU bitmask (upper triangle only) ----------------
__global__ void maskpre_kernel() {
    int b = blockIdx.z;
    int row0 = blockIdx.y * 128;
    int col0 = blockIdx.x * 64;
    if (col0 + 63 <= row0) return;   // sub-diagonal: never read
    __shared__ float4 cbox[64];
    __shared__ float carea[64];
    int t = threadIdx.x; // 128 threads
    if (t < 64) {
        float4 cb = g_boxes[b * PRE_NMS + col0 + t];
        cbox[t] = cb;
        carea[t] = (cb.z - cb.x) * (cb.w - cb.y);
    }
    __syncthreads();
    int r = row0 + t;
    float4 rb = g_boxes[b * PRE_NMS + r];
    float areaR = (rb.z - rb.x) * (rb.w - rb.y);
    u64 bits = 0ULL;
#pragma unroll 8
    for (int jj = 0; jj < 64; ++jj) {
        float4 cb = cbox[jj];
        float ih = fmaxf(fminf(rb.z, cb.z) - fmaxf(rb.x, cb.x), 0.f);
        float iw = fmaxf(fminf(rb.w, cb.w) - fmaxf(rb.y, cb.y), 0.f);
        float inter = ih * iw;
        float iou = inter / (areaR + carea[jj] - inter + 1e-8f);
        if (iou > NMS_THR) bits |= (1ULL << jj);
    }
    g_mask2[(b * PRE2 + r) * NW2 + blockIdx.x] = bits;
}

// ---------------- 5: prefix serial NMS — word-batched decisions ----------------
__global__ void __launch_bounds__(32, 1) nmspre_kernel(float* __restrict__ out) {
    int b = blockIdx.x;
    int lane = threadIdx.x; // 32
    const u64* M = g_mask2 + (size_t)b * PRE2 * NW2;
    __shared__ int list[PROP];
    u64 rem = 0;
    u64 cb0[16], cb1[16], cb2[16], cb3[16];
    const int NCH = PRE2 / 16; // 128 chunks of 16 rows
    // preload chunks 0..2
#pragma unroll
    for (int k = 0; k < 16; ++k) cb0[k] = M[(size_t)(0 * 16 + k) * NW2 + lane];
#pragma unroll
    for (int k = 0; k < 16; ++k) cb1[k] = M[(size_t)(1 * 16 + k) * NW2 + lane];
#pragma unroll
    for (int k = 0; k < 16; ++k) cb2[k] = M[(size_t)(2 * 16 + k) * NW2 + lane];
    int kc = 0;

#define PROCESS_CHUNK(CUR, PFBUF, CHUNK)                                          \
    {                                                                             \
        int chunk = (CHUNK);                                                      \
        int pf = chunk + 3;                                                       \
        if (pf < NCH) {                                                           \
            _Pragma("unroll")                                                     \
            for (int k = 0; k < 16; ++k)                                          \
                PFBUF[k] = M[(size_t)(pf * 16 + k) * NW2 + lane];                 \
        }                                                                         \
        int base = chunk * 16;                                                    \
        int w = base >> 6;                                                        \
        unsigned keptm = 0;                                                       \
        if (lane == w) {                                                          \
            int bp0 = base & 63;                                                  \
            u64 r = rem;                                                          \
            int kcl = kc;                                                         \
            _Pragma("unroll")                                                     \
            for (int k = 0; k < 16; ++k) {                                        \
                if (kcl < PROP && !((r >> (bp0 + k)) & 1ULL)) {                   \
                    keptm |= (1u << k);                                           \
                    r |= CUR[k];                                                  \
                    kcl++;                                                        \
                }                                                                 \
            }                                                                     \
        }                                                                         \
        keptm = __shfl_sync(0xffffffffu, keptm, w);                               \
        _Pragma("unroll")                                                         \
        for (int k = 0; k < 16; ++k)                                              \
            if (keptm & (1u << k)) rem |= CUR[k];                                 \
        if (lane < 16 && ((keptm >> lane) & 1u)) {                                \
            int pos = kc + __popc(keptm & ((1u << lane) - 1u));                   \
            if (pos < PROP) list[pos] = base + lane;                              \
        }                                                                         \
        kc += __popc(keptm);                                                      \
        if (kc >= PROP) goto done;                                                \
    }

    for (int ch = 0; ch < NCH; ch += 4) {
        PROCESS_CHUNK(cb0, cb3, ch + 0)
        PROCESS_CHUNK(cb1, cb0, ch + 1)
        PROCESS_CHUNK(cb2, cb1, ch + 2)
        PROCESS_CHUNK(cb3, cb2, ch + 3)
    }
#undef PROCESS_CHUNK
done:
    __syncwarp();
    if (kc >= PROP) {
        if (lane == 0) g_done[b] = 1;
        const float4* bx = g_boxes + b * PRE_NMS;
        float4* o = (float4*)(out + (size_t)b * PROP * 4);
        for (int r = lane; r < PROP; r += 32) o[r] = bx[list[r]];
    } else {
        if (lane == 0) g_done[b] = 0;
    }
}

// ---------------- 6: fallback full mask (flag-guarded, upper triangle) ---------
__global__ void fbmask_kernel() {
    int b = blockIdx.z;
    if (g_done[b]) return;
    int row0 = blockIdx.y * 128;
    int col0 = blockIdx.x * 64;
    if (col0 + 63 <= row0) return;
    __shared__ float4 cbox[64];
    __shared__ float carea[64];
    int t = threadIdx.x; // 128
    if (t < 64) {
        int c = col0 + t;
        float4 cb = (c < PRE_NMS) ? g_boxes[b * PRE_NMS + c] : make_float4(0.f, 0.f, 0.f, 0.f);
        cbox[t] = cb;
        carea[t] = (cb.z - cb.x) * (cb.w - cb.y);
    }
    __syncthreads();
    int r = row0 + t;
    if (r >= PRE_NMS) return;
    float4 rb = g_boxes[b * PRE_NMS + r];
    float areaR = (rb.z - rb.x) * (rb.w - rb.y);
    u64 bits = 0ULL;
#pragma unroll 8
    for (int jj = 0; jj < 64; ++jj) {
        float4 cb = cbox[jj];
        float ih = fmaxf(fminf(rb.z, cb.z) - fmaxf(rb.x, cb.x), 0.f);
        float iw = fmaxf(fminf(rb.w, cb.w) - fmaxf(rb.y, cb.y), 0.f);
        float inter = ih * iw;
        float iou = inter / (areaR + carea[jj] - inter + 1e-8f);
        if (iou > NMS_THR) bits |= (1ULL << jj);
    }
    g_mask[((size_t)b * PRE_NMS + r) * NWORDS + blockIdx.x] = bits;
}

// ---------------- 7: fallback full serial NMS + scratch cleanup ----------------
__global__ void fbnms_kernel(float* __restrict__ out) {
    if (blockIdx.x >= BATCH) {
        // cleanup blocks: re-zero scratch for the next graph replay
        int start = (blockIdx.x - BATCH) * blockDim.x + threadIdx.x;
        for (int t = start; t < BATCH * NBINS; t += 16 * blockDim.x) {
            g_hist[t] = 0;
            g_binfill[t] = 0;
        }
        if (start == 0) {
            g_cutbin[0] = 0; g_cutbin[1] = 0;
            g_ticket = 0u;
        }
        return;
    }
    int b = blockIdx.x;
    if (g_done[b]) return;
    if (threadIdx.x >= 32) return;
    int lane = threadIdx.x;
    const u64* M = g_mask + (size_t)b * PRE_NMS * NWORDS;
    u64 rem0 = 0, rem1 = 0, rem2 = 0;
    __shared__ int list[PROP];
    int kc = 0;
    int w0 = lane, w1 = lane + 32, w2 = lane + 64;
    for (int i = 0; i < PRE_NMS; ++i) {
        const u64* row = M + (size_t)i * NWORDS;
        u64 c0 = row[w0];
        u64 c1 = (w1 < NWORDS) ? row[w1] : 0ULL;
        u64 c2 = (w2 < NWORDS) ? row[w2] : 0ULL;
        int word = i >> 6, bit = i & 63;
        int src = word & 31, slot = word >> 5;
        u64 mine = (slot == 0) ? rem0 : ((slot == 1) ? rem1 : rem2);
        u64 v = __shfl_sync(0xffffffffu, mine, src);
        if (!((v >> bit) & 1ULL)) {
            if (lane == 0 && kc < PROP) list[kc] = i;
            kc++;
            rem0 |= c0; rem1 |= c1; rem2 |= c2;
            if (kc >= PROP) break;
        }
    }
    __syncwarp();
    const float4* bx = g_boxes + b * PRE_NMS;
    float4* o = (float4*)(out + (size_t)b * PROP * 4);
    for (int r = lane; r < PROP; r += 32) {
        float4 v = make_float4(0.f, 0.f, 0.f, 0.f);
        if (r < kc) v = bx[list[r]];
        o[r] = v;
    }
}

// ---------------- launch ----------------
extern "C" void kernel_launch(void* const* d_in, const int* in_sizes, int n_in,
                              void* d_out, int out_size) {
    (void)in_sizes; (void)n_in; (void)out_size;
    const float4* cls4 = (const float4*)d_in[0];
    const float* rpn_bbox = (const float*)d_in[1];
    const float* anchors = (const float*)d_in[2];
    float* out = (float*)d_out;

    hist_kernel<<<256, 512>>>(cls4);
    {
        int total4 = BATCH * NANCH / 2;
        scatter_kernel<<<(total4 + 255) / 256, 256>>>(cls4);
    }
    {
        dim3 grid(NBINS, BATCH);
        sortbox_kernel<<<grid, 256>>>(rpn_bbox, anchors);
    }
    {
        dim3 grid(NW2, PRE2 / 128, BATCH);       // (32, 16, 2)
        maskpre_kernel<<<grid, 128>>>();
    }
    nmspre_kernel<<<BATCH, 32>>>(out);
    {
        dim3 grid(NWORDS, (PRE_NMS + 127) / 128, BATCH); // (94, 47, 2)
        fbmask_kernel<<<grid, 128>>>();
    }
    fbnms_kernel<<<BATCH + 16, 256>>>(out);
}

// round 5
// speedup vs baseline: 7.5664x; 1.3094x over previous
#include <cuda_runtime.h>
#include <cuda_bf16.h>
#include <cstdint>

#define BATCH 2
#define NANCH 261888
#define PRE_NMS 6000
#define PRE2 1536          // prefix length for fast-path NMS
#define NW2 (PRE2 / 64)    // 24 words per prefix row
#define PROP 1000
#define NMS_THR 0.7f
#define NBINS 4096
#define SCAP 12288
#define BUCKET_CAP 2048
#define SB_GRID 768        // sortbox cutbin-relative grid width

typedef unsigned long long u64;

// ---------------- scratch (zero at module load; re-zeroed by tail kernel) -------
__device__ int g_hist[BATCH * NBINS];
__device__ int g_offset[BATCH * NBINS];
__device__ int g_binfill[BATCH * NBINS];
__device__ int g_cutbin[BATCH];
__device__ int g_done[BATCH];
__device__ unsigned int g_ticket;
__device__ u64 g_sorted[BATCH * SCAP];
__device__ float4 g_boxes[BATCH * PRE_NMS];
__device__ u64 g_mask2[BATCH * PRE2 * NW2];   // 576 KB prefix mask

// ---------------- helpers ----------------
__device__ __forceinline__ int score_bin(float s) {
    int b = (int)(s * (float)NBINS);
    if (b < 0) b = 0;
    if (b > NBINS - 1) b = NBINS - 1;
    return b;
}

// keep ⟺ iou > THR ⟺ (1+THR)*inter > THR*(areaR+areaC+eps)
// (denominator is positive; algebraically identical comparison, no division)
__device__ __forceinline__ bool iou_gt(float4 a, float aR7, float4 c, float cA7) {
    float ih = fmaxf(fminf(a.z, c.z) - fmaxf(a.x, c.x), 0.f);
    float iw = fmaxf(fminf(a.w, c.w) - fmaxf(a.y, c.y), 0.f);
    float inter = ih * iw;
    return 1.7f * inter > aR7 + cA7;
}

// ---------------- 1: histogram + fused suffix-scan (last-block) ----------------
__global__ void hist_kernel(const float4* __restrict__ cls4) {
    __shared__ int h[BATCH * NBINS];
    for (int t = threadIdx.x; t < BATCH * NBINS; t += blockDim.x) h[t] = 0;
    __syncthreads();
    const int total4 = BATCH * NANCH / 2;
    const int half = NANCH / 2;
    for (int t = blockIdx.x * blockDim.x + threadIdx.x; t < total4;
         t += gridDim.x * blockDim.x) {
        int b = t / half;
        float4 v = cls4[t];
        atomicAdd(&h[b * NBINS + score_bin(v.y)], 1);
        atomicAdd(&h[b * NBINS + score_bin(v.w)], 1);
    }
    __syncthreads();
    for (int t = threadIdx.x; t < BATCH * NBINS; t += blockDim.x)
        if (h[t]) atomicAdd(&g_hist[t], h[t]);

    __threadfence();
    __shared__ int is_last;
    if (threadIdx.x == 0)
        is_last = (atomicAdd(&g_ticket, 1u) == gridDim.x - 1) ? 1 : 0;
    __syncthreads();
    if (!is_last) return;

    // suffix scan: 1024 threads, 4 bins each
    __shared__ int sA[1024], sB[1024];
    for (int b = 0; b < BATCH; ++b) {
        int t = threadIdx.x;
        int base = b * NBINS + t * 4;
        int h0 = g_hist[base + 0], h1 = g_hist[base + 1];
        int h2 = g_hist[base + 2], h3 = g_hist[base + 3];
        int sum = h0 + h1 + h2 + h3;
        sA[t] = sum;
        __syncthreads();
        int* src = sA; int* dst = sB;
        for (int d = 1; d < 1024; d <<= 1) {
            int v = src[t];
            if (t + d < 1024) v += src[t + d];
            dst[t] = v;
            __syncthreads();
            int* tmp = src; src = dst; dst = tmp;
        }
        int excl = src[t] - sum;
        int off3 = excl;
        int off2 = off3 + h3;
        int off1 = off2 + h2;
        int off0 = off1 + h1;
        g_offset[base + 0] = off0; g_offset[base + 1] = off1;
        g_offset[base + 2] = off2; g_offset[base + 3] = off3;
        if (off3 + h3 >= PRE_NMS) atomicMax(&g_cutbin[b], t * 4 + 3);
        else if (off2 + h2 >= PRE_NMS) atomicMax(&g_cutbin[b], t * 4 + 2);
        else if (off1 + h1 >= PRE_NMS) atomicMax(&g_cutbin[b], t * 4 + 1);
        else if (off0 + h0 >= PRE_NMS) atomicMax(&g_cutbin[b], t * 4 + 0);
        __syncthreads();
    }
}

// ---------------- 2: scatter candidates to bucket ranges (float4) --------------
__global__ void scatter_kernel(const float4* __restrict__ cls4) {
    const int total4 = BATCH * NANCH / 2;
    const int half = NANCH / 2;
    int t = blockIdx.x * blockDim.x + threadIdx.x;
    if (t >= total4) return;
    int b = t / half;
    int i0 = (t - b * half) * 2;
    float4 v = cls4[t];
    int cut = g_cutbin[b];
#pragma unroll
    for (int e = 0; e < 2; ++e) {
        float s = e ? v.w : v.y;
        int i = i0 + e;
        int q = score_bin(s);
        if (q >= cut) {
            int pos = g_offset[b * NBINS + q] + atomicAdd(&g_binfill[b * NBINS + q], 1);
            if (pos < SCAP) {
                unsigned int sb = __float_as_uint(s);
                g_sorted[b * SCAP + pos] =
                    ((u64)sb << 32) | (u64)(0xFFFFFFFFu - (unsigned)i);
            }
        }
    }
}

// ---------------- 3: per-bucket sort + box decode (cutbin-relative grid) -------
__global__ void sortbox_kernel(const float* __restrict__ rpn_bbox,
                               const float* __restrict__ anchors) {
    int b = blockIdx.y;
    int cut = g_cutbin[b];
    __shared__ u64 s[BUCKET_CAP];
    for (int bin = cut + blockIdx.x; bin < NBINS; bin += SB_GRID) {
        int cnt = g_hist[b * NBINS + bin];
        if (cnt <= 0) continue;
        if (cnt > BUCKET_CAP) cnt = BUCKET_CAP;
        int off = g_offset[b * NBINS + bin];
        if (off >= PRE_NMS) continue;
        int P = 1;
        while (P < cnt) P <<= 1;
        const u64* src = g_sorted + (size_t)b * SCAP + off;
        for (int t = threadIdx.x; t < P; t += blockDim.x)
            s[t] = (t < cnt) ? src[t] : 0ULL;
        __syncthreads();
        if (cnt > 1) {
            for (int k = 2; k <= P; k <<= 1) {
                for (int j = k >> 1; j > 0; j >>= 1) {
                    for (int i = threadIdx.x; i < P; i += blockDim.x) {
                        int ixj = i ^ j;
                        if (ixj > i) {
                            bool dir = ((i & k) == 0);
                            u64 a = s[i], c = s[ixj];
                            if ((a < c) == dir) { s[i] = c; s[ixj] = a; }
                        }
                    }
                    __syncthreads();
                }
            }
        }
        for (int t = threadIdx.x; t < cnt; t += blockDim.x) {
            int rank = off + t;
            if (rank >= PRE_NMS) continue;
            unsigned int low = (unsigned int)(s[t] & 0xFFFFFFFFu);
            int idx = (int)(0xFFFFFFFFu - low);
            size_t base = ((size_t)b * NANCH + (size_t)idx) * 4;
            float a0 = anchors[base + 0], a1 = anchors[base + 1];
            float a2 = anchors[base + 2], a3 = anchors[base + 3];
            float d0 = rpn_bbox[base + 0] * 0.1f;
            float d1 = rpn_bbox[base + 1] * 0.1f;
            float d2 = rpn_bbox[base + 2] * 0.2f;
            float d3 = rpn_bbox[base + 3] * 0.2f;
            float h = a2 - a0, w = a3 - a1;
            float cy = a0 + 0.5f * h + d0 * h;
            float cx = a1 + 0.5f * w + d1 * w;
            h = h * expf(d2);
            w = w * expf(d3);
            float y1 = cy - 0.5f * h;
            float x1 = cx - 0.5f * w;
            float y2 = y1 + h;
            float x2 = x1 + w;
            y1 = fminf(fmaxf(y1, 0.f), 1.f);
            x1 = fminf(fmaxf(x1, 0.f), 1.f);
            y2 = fminf(fmaxf(y2, 0.f), 1.f);
            x2 = fminf(fmaxf(x2, 0.f), 1.f);
            g_boxes[b * PRE_NMS + rank] = make_float4(y1, x1, y2, x2);
        }
        __syncthreads();
    }
}

// ---------------- 4: prefix IoU bitmask (upper triangle, no division) ----------
__global__ void maskpre_kernel() {
    int b = blockIdx.z;
    int row0 = blockIdx.y * 128;
    int col0 = blockIdx.x * 64;
    if (col0 + 63 <= row0) return;   // sub-diagonal: never read
    __shared__ float4 cbox[64];
    __shared__ float cA7[64];        // 0.7*(area+eps)
    int t = threadIdx.x;             // 128 threads
    if (t < 64) {
        float4 cb = g_boxes[b * PRE_NMS + col0 + t];
        cbox[t] = cb;
        cA7[t] = 0.7f * ((cb.z - cb.x) * (cb.w - cb.y) + 1e-8f);
    }
    __syncthreads();
    int r = row0 + t;
    float4 rb = g_boxes[b * PRE_NMS + r];
    float aR7 = 0.7f * ((rb.z - rb.x) * (rb.w - rb.y));
    unsigned lo = 0, hi = 0;
#pragma unroll
    for (int jj = 0; jj < 32; ++jj)
        if (iou_gt(rb, aR7, cbox[jj], cA7[jj])) lo |= (1u << jj);
#pragma unroll
    for (int jj = 0; jj < 32; ++jj)
        if (iou_gt(rb, aR7, cbox[32 + jj], cA7[32 + jj])) hi |= (1u << jj);
    g_mask2[(b * PRE2 + r) * NW2 + blockIdx.x] = ((u64)hi << 32) | lo;
}

// ---------------- 5: prefix serial NMS — word-batched decisions ----------------
__global__ void __launch_bounds__(32, 1) nmspre_kernel(float* __restrict__ out) {
    int b = blockIdx.x;
    int lane = threadIdx.x;
    int ll = (lane < NW2) ? lane : 0;
    const u64* M = g_mask2 + (size_t)b * PRE2 * NW2;
    __shared__ int list[PROP];
    u64 rem = 0;
    u64 cb0[16], cb1[16], cb2[16], cb3[16];
    const int NCH = PRE2 / 16;  // 96 chunks
#pragma unroll
    for (int k = 0; k < 16; ++k) cb0[k] = M[(size_t)(0 * 16 + k) * NW2 + ll];
#pragma unroll
    for (int k = 0; k < 16; ++k) cb1[k] = M[(size_t)(1 * 16 + k) * NW2 + ll];
#pragma unroll
    for (int k = 0; k < 16; ++k) cb2[k] = M[(size_t)(2 * 16 + k) * NW2 + ll];
    int kc = 0;

#define PROCESS_CHUNK(CUR, PFBUF, CHUNK)                                          \
    {                                                                             \
        int chunk = (CHUNK);                                                      \
        int pf = chunk + 3;                                                       \
        if (pf < NCH) {                                                           \
            _Pragma("unroll")                                                     \
            for (int k = 0; k < 16; ++k)                                          \
                PFBUF[k] = M[(size_t)(pf * 16 + k) * NW2 + ll];                   \
        }                                                                         \
        int base = chunk * 16;                                                    \
        int w = base >> 6;                                                        \
        unsigned keptm = 0;                                                       \
        if (lane == w) {                                                          \
            int bp0 = base & 63;                                                  \
            u64 r = rem;                                                          \
            int kcl = kc;                                                         \
            _Pragma("unroll")                                                     \
            for (int k = 0; k < 16; ++k) {                                        \
                if (kcl < PROP && !((r >> (bp0 + k)) & 1ULL)) {                   \
                    keptm |= (1u << k);                                           \
                    r |= CUR[k];                                                  \
                    kcl++;                                                        \
                }                                                                 \
            }                                                                     \
        }                                                                         \
        keptm = __shfl_sync(0xffffffffu, keptm, w);                               \
        _Pragma("unroll")                                                         \
        for (int k = 0; k < 16; ++k)                                              \
            if (keptm & (1u << k)) rem |= CUR[k];                                 \
        if (lane < 16 && ((keptm >> lane) & 1u)) {                                \
            int pos = kc + __popc(keptm & ((1u << lane) - 1u));                   \
            if (pos < PROP) list[pos] = base + lane;                              \
        }                                                                         \
        kc += __popc(keptm);                                                      \
        if (kc >= PROP) goto done;                                                \
    }

    for (int ch = 0; ch < NCH; ch += 4) {
        PROCESS_CHUNK(cb0, cb3, ch + 0)
        PROCESS_CHUNK(cb1, cb0, ch + 1)
        PROCESS_CHUNK(cb2, cb1, ch + 2)
        PROCESS_CHUNK(cb3, cb2, ch + 3)
    }
#undef PROCESS_CHUNK
done:
    __syncwarp();
    if (kc >= PROP) {
        if (lane == 0) g_done[b] = 1;
        const float4* bx = g_boxes + b * PRE_NMS;
        float4* o = (float4*)(out + (size_t)b * PROP * 4);
        for (int r = lane; r < PROP; r += 32) o[r] = bx[list[r]];
    } else {
        if (lane == 0) g_done[b] = 0;
    }
}

// ---------------- 6: fallback direct NMS (flag-guarded) + cleanup --------------
__global__ void fb_kernel(float* __restrict__ out) {
    if (blockIdx.x >= BATCH) {
        // cleanup: re-zero scratch for the next graph replay
        int start = (blockIdx.x - BATCH) * blockDim.x + threadIdx.x;
        for (int t = start; t < BATCH * NBINS; t += 8 * blockDim.x) {
            g_hist[t] = 0;
            g_binfill[t] = 0;
        }
        if (start == 0) {
            g_cutbin[0] = 0; g_cutbin[1] = 0;
            g_ticket = 0u;
        }
        return;
    }
    int b = blockIdx.x;
    if (g_done[b]) return;

    // direct sequential NMS over all 6000 boxes (exact; rarely taken)
    __shared__ float4 kept[PROP];
    __shared__ float keptA7[PROP];
    const float4* bx = g_boxes + b * PRE_NMS;
    int kc = 0;
    for (int i = 0; i < PRE_NMS && kc < PROP; ++i) {
        float4 bi = bx[i];
        float aR7 = 0.7f * ((bi.z - bi.x) * (bi.w - bi.y));
        int sup = 0;
        for (int j = threadIdx.x; j < kc; j += blockDim.x)
            if (iou_gt(bi, aR7, kept[j], keptA7[j])) sup = 1;
        sup = __syncthreads_or(sup);
        if (!sup) {
            if (threadIdx.x == 0) {
                kept[kc] = bi;
                keptA7[kc] = 0.7f * ((bi.z - bi.x) * (bi.w - bi.y) + 1e-8f);
            }
            kc++;
            __syncthreads();
        }
    }
    float4* o = (float4*)(out + (size_t)b * PROP * 4);
    for (int r = threadIdx.x; r < PROP; r += blockDim.x) {
        float4 v = make_float4(0.f, 0.f, 0.f, 0.f);
        if (r < kc) v = kept[r];
        o[r] = v;
    }
}

// ---------------- launch ----------------
extern "C" void kernel_launch(void* const* d_in, const int* in_sizes, int n_in,
                              void* d_out, int out_size) {
    (void)in_sizes; (void)n_in; (void)out_size;
    const float4* cls4 = (const float4*)d_in[0];
    const float* rpn_bbox = (const float*)d_in[1];
    const float* anchors = (const float*)d_in[2];
    float* out = (float*)d_out;

    hist_kernel<<<132, 1024>>>(cls4);
    {
        int total4 = BATCH * NANCH / 2;
        scatter_kernel<<<(total4 + 255) / 256, 256>>>(cls4);
    }
    {
        dim3 grid(SB_GRID, BATCH);
        sortbox_kernel<<<grid, 128>>>(rpn_bbox, anchors);
    }
    {
        dim3 grid(NW2, PRE2 / 128, BATCH);   // (24, 12, 2)
        maskpre_kernel<<<grid, 128>>>();
    }
    nmspre_kernel<<<BATCH, 32>>>(out);
    fb_kernel<<<BATCH + 8, 256>>>(out);
}

// round 6
// speedup vs baseline: 7.8047x; 1.0315x over previous
#include <cuda_runtime.h>
#include <cuda_bf16.h>
#include <cstdint>

#define BATCH 2
#define NANCH 261888
#define PRE_NMS 6000
#define PRE2 1536          // prefix length for fast-path NMS
#define NW2 (PRE2 / 64)    // 24 words per prefix row
#define PROP 1000
#define NMS_THR 0.7f
#define NBINS 2048
#define SCAP 12288
#define BUCKET_CAP 2048
#define SB_GRID 128        // sortbox cutbin-relative grid width

typedef unsigned long long u64;

// ---------------- scratch (zero at module load; re-zeroed by tail kernel) -------
__device__ int g_hist[BATCH * NBINS];
__device__ int g_offset[BATCH * NBINS];
__device__ int g_binfill[BATCH * NBINS];
__device__ int g_cutbin[BATCH];
__device__ unsigned int g_ticket;
__device__ u64 g_sorted[BATCH * SCAP];
__device__ float4 g_boxes[BATCH * PRE_NMS];
__device__ u64 g_mask2[BATCH * PRE2 * NW2];   // 576 KB prefix mask

// ---------------- helpers ----------------
__device__ __forceinline__ int score_bin(float s) {
    int b = (int)(s * (float)NBINS);
    if (b < 0) b = 0;
    if (b > NBINS - 1) b = NBINS - 1;
    return b;
}

// keep ⟺ iou > THR ⟺ (1+THR)*inter > THR*(areaR+areaC+eps)  (denominator > 0)
__device__ __forceinline__ bool iou_gt(float4 a, float aR7, float4 c, float cA7) {
    float ih = fmaxf(fminf(a.z, c.z) - fmaxf(a.x, c.x), 0.f);
    float iw = fmaxf(fminf(a.w, c.w) - fmaxf(a.y, c.y), 0.f);
    float inter = ih * iw;
    return 1.7f * inter > aR7 + cA7;
}

// ---------------- 1: histogram + fused suffix-scan (last-block) ----------------
__global__ void hist_kernel(const float4* __restrict__ cls4) {
    __shared__ int h[BATCH * NBINS];   // 16 KB
    for (int t = threadIdx.x; t < BATCH * NBINS; t += blockDim.x) h[t] = 0;
    __syncthreads();
    const int total4 = BATCH * NANCH / 2;
    const int half = NANCH / 2;
    for (int t = blockIdx.x * blockDim.x + threadIdx.x; t < total4;
         t += gridDim.x * blockDim.x) {
        int b = t / half;
        float4 v = cls4[t];
        atomicAdd(&h[b * NBINS + score_bin(v.y)], 1);
        atomicAdd(&h[b * NBINS + score_bin(v.w)], 1);
    }
    __syncthreads();
    for (int t = threadIdx.x; t < BATCH * NBINS; t += blockDim.x)
        if (h[t]) atomicAdd(&g_hist[t], h[t]);

    __threadfence();
    __shared__ int is_last;
    if (threadIdx.x == 0)
        is_last = (atomicAdd(&g_ticket, 1u) == gridDim.x - 1) ? 1 : 0;
    __syncthreads();
    if (!is_last) return;

    // suffix scan: 1024 threads, 2 bins each
    __shared__ int sA[1024], sB[1024];
    for (int b = 0; b < BATCH; ++b) {
        int t = threadIdx.x;
        int base = b * NBINS + t * 2;
        int h0 = g_hist[base + 0], h1 = g_hist[base + 1];
        int sum = h0 + h1;
        sA[t] = sum;
        __syncthreads();
        int* src = sA; int* dst = sB;
        for (int d = 1; d < 1024; d <<= 1) {
            int v = src[t];
            if (t + d < 1024) v += src[t + d];
            dst[t] = v;
            __syncthreads();
            int* tmp = src; src = dst; dst = tmp;
        }
        int excl = src[t] - sum;
        int off1 = excl;
        int off0 = off1 + h1;
        g_offset[base + 0] = off0; g_offset[base + 1] = off1;
        if (off1 + h1 >= PRE_NMS) atomicMax(&g_cutbin[b], t * 2 + 1);
        else if (off0 + h0 >= PRE_NMS) atomicMax(&g_cutbin[b], t * 2 + 0);
        __syncthreads();
    }
}

// ---------------- 2: scatter candidates to bucket ranges (float4) --------------
__global__ void scatter_kernel(const float4* __restrict__ cls4) {
    const int total4 = BATCH * NANCH / 2;
    const int half = NANCH / 2;
    int t = blockIdx.x * blockDim.x + threadIdx.x;
    if (t >= total4) return;
    int b = t / half;
    int i0 = (t - b * half) * 2;
    float4 v = cls4[t];
    int cut = g_cutbin[b];
#pragma unroll
    for (int e = 0; e < 2; ++e) {
        float s = e ? v.w : v.y;
        int i = i0 + e;
        int q = score_bin(s);
        if (q >= cut) {
            int pos = g_offset[b * NBINS + q] + atomicAdd(&g_binfill[b * NBINS + q], 1);
            if (pos < SCAP) {
                unsigned int sb = __float_as_uint(s);
                g_sorted[b * SCAP + pos] =
                    ((u64)sb << 32) | (u64)(0xFFFFFFFFu - (unsigned)i);
            }
        }
    }
}

// ---------------- 3: per-bucket sort + box decode (cutbin-relative grid) -------
__global__ void sortbox_kernel(const float* __restrict__ rpn_bbox,
                               const float* __restrict__ anchors) {
    int b = blockIdx.y;
    int cut = g_cutbin[b];
    __shared__ u64 s[BUCKET_CAP];
    for (int bin = cut + blockIdx.x; bin < NBINS; bin += SB_GRID) {
        int cnt = g_hist[b * NBINS + bin];
        if (cnt <= 0) continue;
        if (cnt > BUCKET_CAP) cnt = BUCKET_CAP;
        int off = g_offset[b * NBINS + bin];
        if (off >= PRE_NMS) continue;
        int P = 1;
        while (P < cnt) P <<= 1;
        const u64* src = g_sorted + (size_t)b * SCAP + off;
        for (int t = threadIdx.x; t < P; t += blockDim.x)
            s[t] = (t < cnt) ? src[t] : 0ULL;
        __syncthreads();
        if (cnt > 1) {
            for (int k = 2; k <= P; k <<= 1) {
                for (int j = k >> 1; j > 0; j >>= 1) {
                    for (int i = threadIdx.x; i < P; i += blockDim.x) {
                        int ixj = i ^ j;
                        if (ixj > i) {
                            bool dir = ((i & k) == 0);
                            u64 a = s[i], c = s[ixj];
                            if ((a < c) == dir) { s[i] = c; s[ixj] = a; }
                        }
                    }
                    __syncthreads();
                }
            }
        }
        for (int t = threadIdx.x; t < cnt; t += blockDim.x) {
            int rank = off + t;
            if (rank >= PRE_NMS) continue;
            unsigned int low = (unsigned int)(s[t] & 0xFFFFFFFFu);
            int idx = (int)(0xFFFFFFFFu - low);
            size_t base = ((size_t)b * NANCH + (size_t)idx) * 4;
            float a0 = anchors[base + 0], a1 = anchors[base + 1];
            float a2 = anchors[base + 2], a3 = anchors[base + 3];
            float d0 = rpn_bbox[base + 0] * 0.1f;
            float d1 = rpn_bbox[base + 1] * 0.1f;
            float d2 = rpn_bbox[base + 2] * 0.2f;
            float d3 = rpn_bbox[base + 3] * 0.2f;
            float h = a2 - a0, w = a3 - a1;
            float cy = a0 + 0.5f * h + d0 * h;
            float cx = a1 + 0.5f * w + d1 * w;
            h = h * expf(d2);
            w = w * expf(d3);
            float y1 = cy - 0.5f * h;
            float x1 = cx - 0.5f * w;
            float y2 = y1 + h;
            float x2 = x1 + w;
            y1 = fminf(fmaxf(y1, 0.f), 1.f);
            x1 = fminf(fmaxf(x1, 0.f), 1.f);
            y2 = fminf(fmaxf(y2, 0.f), 1.f);
            x2 = fminf(fmaxf(x2, 0.f), 1.f);
            g_boxes[b * PRE_NMS + rank] = make_float4(y1, x1, y2, x2);
        }
        __syncthreads();
    }
}

// ---------------- 4: prefix IoU bitmask (upper triangle, 2 rows/thread) --------
__global__ void maskpre_kernel() {
    int b = blockIdx.z;
    int row0 = blockIdx.y * 256;
    int col0 = blockIdx.x * 64;
    if (col0 + 63 <= row0) return;   // whole block sub-diagonal: never read
    __shared__ float4 cbox[64];
    __shared__ float cA7[64];
    int t = threadIdx.x;             // 128 threads
    if (t < 64) {
        float4 cb = g_boxes[b * PRE_NMS + col0 + t];
        cbox[t] = cb;
        cA7[t] = 0.7f * ((cb.z - cb.x) * (cb.w - cb.y) + 1e-8f);
    }
    __syncthreads();
    int rA = row0 + t;
    int rB = rA + 128;
    float4 ba = g_boxes[b * PRE_NMS + rA];
    float4 bb = g_boxes[b * PRE_NMS + rB];
    float a7 = 0.7f * ((ba.z - ba.x) * (ba.w - ba.y));
    float b7 = 0.7f * ((bb.z - bb.x) * (bb.w - bb.y));
    unsigned alo = 0, ahi = 0, blo = 0, bhi = 0;
#pragma unroll
    for (int jj = 0; jj < 32; ++jj) {
        float4 cb = cbox[jj];
        float c7 = cA7[jj];
        if (iou_gt(ba, a7, cb, c7)) alo |= (1u << jj);
        if (iou_gt(bb, b7, cb, c7)) blo |= (1u << jj);
    }
#pragma unroll
    for (int jj = 0; jj < 32; ++jj) {
        float4 cb = cbox[32 + jj];
        float c7 = cA7[32 + jj];
        if (iou_gt(ba, a7, cb, c7)) ahi |= (1u << jj);
        if (iou_gt(bb, b7, cb, c7)) bhi |= (1u << jj);
    }
    // sub-diagonal words per-row are never read: skip their write (stale ok)
    if (col0 + 63 > rA)
        g_mask2[(b * PRE2 + rA) * NW2 + blockIdx.x] = ((u64)ahi << 32) | alo;
    g_mask2[(b * PRE2 + rB) * NW2 + blockIdx.x] = ((u64)bhi << 32) | blo;
}

// ---------------- 5: NMS (prefix fast path + direct fallback) + cleanup --------
__global__ void nms_kernel(float* __restrict__ out) {
    if (blockIdx.x >= BATCH) {
        // cleanup blocks: re-zero scratch for the next graph replay
        int start = (blockIdx.x - BATCH) * blockDim.x + threadIdx.x;
        for (int t = start; t < BATCH * NBINS; t += 8 * blockDim.x) {
            g_hist[t] = 0;
            g_binfill[t] = 0;
        }
        if (start == 0) {
            g_cutbin[0] = 0; g_cutbin[1] = 0;
            g_ticket = 0u;
        }
        return;
    }
    int b = blockIdx.x;
    __shared__ int list[PROP];
    __shared__ int s_kc;

    if (threadIdx.x < 32) {
        int lane = threadIdx.x;
        int ll = (lane < NW2) ? lane : 0;
        const u64* M = g_mask2 + (size_t)b * PRE2 * NW2;
        u64 rem = 0;
        u64 cb0[16], cb1[16], cb2[16], cb3[16];
        const int NCH = PRE2 / 16;  // 96 chunks
#pragma unroll
        for (int k = 0; k < 16; ++k) cb0[k] = M[(size_t)(0 * 16 + k) * NW2 + ll];
#pragma unroll
        for (int k = 0; k < 16; ++k) cb1[k] = M[(size_t)(1 * 16 + k) * NW2 + ll];
#pragma unroll
        for (int k = 0; k < 16; ++k) cb2[k] = M[(size_t)(2 * 16 + k) * NW2 + ll];
        int kc = 0;

#define PROCESS_CHUNK(CUR, PFBUF, CHUNK)                                          \
    {                                                                             \
        int chunk = (CHUNK);                                                      \
        int pf = chunk + 3;                                                       \
        if (pf < NCH) {                                                           \
            _Pragma("unroll")                                                     \
            for (int k = 0; k < 16; ++k)                                          \
                PFBUF[k] = M[(size_t)(pf * 16 + k) * NW2 + ll];                   \
        }                                                                         \
        int base = chunk * 16;                                                    \
        int w = base >> 6;                                                        \
        unsigned keptm = 0;                                                       \
        if (lane == w) {                                                          \
            int bp0 = base & 63;                                                  \
            u64 r = rem;                                                          \
            int kcl = kc;                                                         \
            _Pragma("unroll")                                                     \
            for (int k = 0; k < 16; ++k) {                                        \
                if (kcl < PROP && !((r >> (bp0 + k)) & 1ULL)) {                   \
                    keptm |= (1u << k);                                           \
                    r |= CUR[k];                                                  \
                    kcl++;                                                        \
                }                                                                 \
            }                                                                     \
        }                                                                         \
        keptm = __shfl_sync(0xffffffffu, keptm, w);                               \
        _Pragma("unroll")                                                         \
        for (int k = 0; k < 16; ++k)                                              \
            if (keptm & (1u << k)) rem |= CUR[k];                                 \
        if (lane < 16 && ((keptm >> lane) & 1u)) {                                \
            int pos = kc + __popc(keptm & ((1u << lane) - 1u));                   \
            if (pos < PROP) list[pos] = base + lane;                              \
        }                                                                         \
        kc += __popc(keptm);                                                      \
        if (kc >= PROP) goto done;                                                \
    }

        for (int ch = 0; ch < NCH; ch += 4) {
            PROCESS_CHUNK(cb0, cb3, ch + 0)
            PROCESS_CHUNK(cb1, cb0, ch + 1)
            PROCESS_CHUNK(cb2, cb1, ch + 2)
            PROCESS_CHUNK(cb3, cb2, ch + 3)
        }
#undef PROCESS_CHUNK
done:
        if (lane == 0) s_kc = kc;
    }
    __syncthreads();

    int kc = s_kc;
    const float4* bx = g_boxes + b * PRE_NMS;
    float4* o = (float4*)(out + (size_t)b * PROP * 4);
    if (kc >= PROP) {
        for (int r = threadIdx.x; r < PROP; r += blockDim.x) o[r] = bx[list[r]];
        return;
    }

    // fallback: exact direct sequential NMS over all 6000 boxes (rarely taken)
    __shared__ float4 kept[PROP];
    __shared__ float keptA7[PROP];
    int kk = 0;
    for (int i = 0; i < PRE_NMS && kk < PROP; ++i) {
        float4 bi = bx[i];
        float aR7 = 0.7f * ((bi.z - bi.x) * (bi.w - bi.y));
        int sup = 0;
        for (int j = threadIdx.x; j < kk; j += blockDim.x)
            if (iou_gt(bi, aR7, kept[j], keptA7[j])) sup = 1;
        sup = __syncthreads_or(sup);
        if (!sup) {
            if (threadIdx.x == 0) {
                kept[kk] = bi;
                keptA7[kk] = 0.7f * ((bi.z - bi.x) * (bi.w - bi.y) + 1e-8f);
            }
            kk++;
            __syncthreads();
        }
    }
    for (int r = threadIdx.x; r < PROP; r += blockDim.x) {
        float4 v = make_float4(0.f, 0.f, 0.f, 0.f);
        if (r < kk) v = kept[r];
        o[r] = v;
    }
}

// ---------------- launch ----------------
extern "C" void kernel_launch(void* const* d_in, const int* in_sizes, int n_in,
                              void* d_out, int out_size) {
    (void)in_sizes; (void)n_in; (void)out_size;
    const float4* cls4 = (const float4*)d_in[0];
    const float* rpn_bbox = (const float*)d_in[1];
    const float* anchors = (const float*)d_in[2];
    float* out = (float*)d_out;

    hist_kernel<<<64, 1024>>>(cls4);
    {
        int total4 = BATCH * NANCH / 2;
        scatter_kernel<<<(total4 + 255) / 256, 256>>>(cls4);
    }
    {
        dim3 grid(SB_GRID, BATCH);
        sortbox_kernel<<<grid, 128>>>(rpn_bbox, anchors);
    }
    {
        dim3 grid(NW2, PRE2 / 256, BATCH);   // (24, 6, 2)
        maskpre_kernel<<<grid, 128>>>();
    }
    nms_kernel<<<BATCH + 8, 256>>>(out);
}